// round 3
// baseline (speedup 1.0000x reference)
#include <cuda_runtime.h>
#include <cuda_bf16.h>

// ============================================================================
// CapLayerLP: 20-iter Mehrotra predictor-corrector PDIP QP, n=1024, m=2051.
// K = eps*I + diag(z1/s1+z2/s2) + w0*11^T + (wA+wB)*ff^T  (diag + rank-2)
// -> Woodbury solve with 2x2 capacitance. One block, 256 thr x 4 coords.
//
// Round-3 changes (latency-bound per ncu: issue=7%, regs=224, DRAM=0):
//  * ALL threads redundantly do the scalar algebra after each reduction
//    (identical values) -> no thread-0 serial section, no broadcast barrier.
//  * mu_aff folded into pass 3 via quadratic expansion -> 5 rounds/iter.
//  * double-buffered reduction scratch -> exactly 1 barrier per round
//    (5 __syncthreads per iteration, was 12).
//  * division-free affine z-ratio: (-dz)/z = 1 + ds/s.
// ============================================================================

#define NV    1024
#define T     256
#define VPT   4
#define NW    (T/32)      // 8 warps
#define MCON  2051.0
#define IMCON (1.0/2051.0)
#define EPSR  1e-4
#define CCAP  10.0
#define ITERS 20

__device__ __forceinline__ double wsum(double v) {
#pragma unroll
    for (int o = 16; o > 0; o >>= 1) v += __shfl_down_sync(0xffffffffu, v, o);
    return v;
}
__device__ __forceinline__ double wmaxr(double v) {
#pragma unroll
    for (int o = 16; o > 0; o >>= 1) v = fmax(v, __shfl_down_sync(0xffffffffu, v, o));
    return v;
}
// stage-2: every thread reads the 8 warp partials and butterfly-reduces,
// so ALL lanes of ALL warps end up with the total (no broadcast needed).
__device__ __forceinline__ double b8sum(const double* p, int lane) {
    double v = p[lane & 7];
#pragma unroll
    for (int o = 4; o > 0; o >>= 1) v += __shfl_xor_sync(0xffffffffu, v, o);
    return v;
}
__device__ __forceinline__ double b8max(const double* p, int lane) {
    double v = p[lane & 7];
#pragma unroll
    for (int o = 4; o > 0; o >>= 1) v = fmax(v, __shfl_xor_sync(0xffffffffu, v, o));
    return v;
}

__global__ void __launch_bounds__(T, 1)
pdip_kernel(const float* __restrict__ xin, const int* __restrict__ male,
            float* __restrict__ out)
{
    const int i    = threadIdx.x;
    const int lane = i & 31;
    const int wid  = i >> 5;

    __shared__ double wb[2][6][NW];   // double-buffered reduction scratch

    // ---- per-thread vector state (4 coords) ----
    double pi[VPT], fi[VPT];
    double xi[VPT], s1[VPT], z1[VPT], s2[VPT], z2[VPT];
#pragma unroll
    for (int k = 0; k < VPT; ++k) {
        int c = i + k * T;
        pi[k] = -(double)xin[c];
        fi[k] = (double)male[c];
        xi[k] = 0.0; s1[k] = 1.0; z1[k] = 1.0; s2[k] = 1.0; z2[k] = 1.0;
    }

    // ---- init: n_male -> h scalars (replicated in every thread) ----
    {
        double v = wsum(fi[0] + fi[1] + fi[2] + fi[3]);
        if (lane == 0) wb[0][0][wid] = v;
    }
    __syncthreads();
    const double nm = b8sum(wb[0][0], lane);
    const double hA = CCAP * nm / (double)NV + 1.0;
    const double hB = -(CCAP * nm / (double)NV);

    // replicated scalar state
    double s0 = 1.0, sA = 1.0, sB = 1.0;
    double z0 = 1.0, zA = 1.0, zB = 1.0;

    int rb = 1;   // reduction buffer parity (init used buffer 0)

    for (int it = 0; it < ITERS; ++it) {
        // =============== Round A: diagonal, residual sums ===============
        double invs1[VPT], invs2[VPT], invD[VPT];
        double a0 = 0, a1 = 0, a2 = 0, a3 = 0, a4 = 0;
#pragma unroll
        for (int k = 0; k < VPT; ++k) {
            invs1[k] = 1.0 / s1[k];
            invs2[k] = 1.0 / s2[k];
            double w1 = z1[k] * invs1[k], w2 = z2[k] * invs2[k];
            invD[k] = 1.0 / (EPSR + w1 + w2);
            a0 += xi[k];
            a1 += fi[k] * xi[k];
            a2 += s1[k] * z1[k] + s2[k] * z2[k];
            a3 += invD[k];
            a4 += fi[k] * invD[k];
        }
        a0 = wsum(a0); a1 = wsum(a1); a2 = wsum(a2); a3 = wsum(a3); a4 = wsum(a4);
        if (lane == 0) {
            wb[rb][0][wid]=a0; wb[rb][1][wid]=a1; wb[rb][2][wid]=a2;
            wb[rb][3][wid]=a3; wb[rb][4][wid]=a4;
        }
        __syncthreads();
        const double sumx = b8sum(wb[rb][0], lane);
        const double fx   = b8sum(wb[rb][1], lane);
        const double szv  = b8sum(wb[rb][2], lane);
        const double SiD  = b8sum(wb[rb][3], lane);
        const double SfD  = b8sum(wb[rb][4], lane);
        rb ^= 1;

        // replicated scalar algebra (every thread; overlaps with round B vec work)
        const double rp0 = sumx + s0 - CCAP;
        const double rpA =  fx + sA - hA;
        const double rpB = -fx + sB - hB;
        const double SZTOT = szv + s0*z0 + sA*zA + sB*zB;
        const double mu  = SZTOT * IMCON;
        const double is0 = 1.0/s0, isA = 1.0/sA, isB = 1.0/sB;
        const double iz0 = 1.0/z0, izA = 1.0/zA, izB = 1.0/zB;
        const double w0 = z0*is0, wA = zA*isA, wB = zB*isB;
        double T0 = w0*rp0 - z0;
        double TA = wA*rpA - zA;
        double TB = wB*rpB - zB;
        const double M11 = s0*iz0 + SiD;          // 1/w0 = s0/z0
        const double M22 = 1.0/(wA + wB) + SfD;
        const double M12 = SfD;
        const double detinv = 1.0/(M11*M22 - M12*M12);

        // =============== Round B: predictor rhs, Woodbury sums ===============
        double g[VPT];
        {
            double b0 = 0, b1 = 0;
#pragma unroll
            for (int k = 0; k < VPT; ++k) {
                double w1 = z1[k] * invs1[k], w2 = z2[k] * invs2[k];
                double rp1 = s1[k] - xi[k];
                double rp2 = xi[k] + s2[k] - 1.0;
                double rx  = EPSR*xi[k] + pi[k] + (z0 - z1[k] + z2[k] + fi[k]*(zA - zB));
                double rhs = -(rx + T0 - (w1*rp1 - z1[k]) + (w2*rp2 - z2[k]) + fi[k]*(TA - TB));
                g[k] = rhs * invD[k];
                b0 += g[k];
                b1 += fi[k] * g[k];
            }
            b0 = wsum(b0); b1 = wsum(b1);
            if (lane == 0) { wb[rb][0][wid] = b0; wb[rb][1][wid] = b1; }
        }
        __syncthreads();
        {
            const double u1 = b8sum(wb[rb][0], lane);
            const double uf = b8sum(wb[rb][1], lane);
            rb ^= 1;
            const double Y1 = (M22*u1 - M12*uf) * detinv;
            const double Y2 = (M11*uf - M12*u1) * detinv;

            // =============== Round C: affine dir + step + mu_aff sums ========
            double c0 = 0, c1 = 0, cS1 = 0, cS2 = 0, mqs = 0, mqz = 0;
#pragma unroll
            for (int k = 0; k < VPT; ++k) {
                double dx = g[k] - (Y1 + fi[k]*Y2) * invD[k];
                g[k] = dx;                               // keep affine dx
                double rp1 = s1[k] - xi[k];
                double rp2 = xi[k] + s2[k] - 1.0;
                double w1 = z1[k] * invs1[k], w2 = z2[k] * invs2[k];
                double ds1 = dx - rp1,  ds2 = -rp2 - dx;
                double dz1 = -z1[k] - w1*ds1;
                double dz2 = -z2[k] - w2*ds2;
                mqs = fmax(mqs, fmax(fmax(-ds1,0.0)*invs1[k], fmax(-ds2,0.0)*invs2[k]));
                // affine identity: (-dz)/z = 1 + ds/s  (division-free)
                mqz = fmax(mqz, fmax(fmax(1.0 + ds1*invs1[k], 0.0),
                                     fmax(1.0 + ds2*invs2[k], 0.0)));
                c0 += dx;
                c1 += fi[k] * dx;
                cS1 += s1[k]*dz1 + z1[k]*ds1 + s2[k]*dz2 + z2[k]*ds2;
                cS2 += ds1*dz1 + ds2*dz2;
            }
            c0 = wsum(c0); c1 = wsum(c1); cS1 = wsum(cS1); cS2 = wsum(cS2);
            mqs = wmaxr(mqs); mqz = wmaxr(mqz);
            if (lane == 0) {
                wb[rb][0][wid]=c0; wb[rb][1][wid]=c1; wb[rb][2][wid]=cS1;
                wb[rb][3][wid]=cS2; wb[rb][4][wid]=mqs; wb[rb][5][wid]=mqz;
            }
        }
        __syncthreads();
        double smu, rsz0, rszA, rszB;
        {
            const double sdx = b8sum(wb[rb][0], lane);
            const double fdx = b8sum(wb[rb][1], lane);
            const double S1v = b8sum(wb[rb][2], lane);
            const double S2v = b8sum(wb[rb][3], lane);
            double mqs = b8max(wb[rb][4], lane);
            double mqz = b8max(wb[rb][5], lane);
            rb ^= 1;
            const double ds0 = -rp0 - sdx;
            const double dsA = -rpA - fdx;
            const double dsB = -rpB + fdx;
            const double dz0 = -z0 - w0*ds0;
            const double dzA = -zA - wA*dsA;
            const double dzB = -zB - wB*dsB;
            mqs = fmax(mqs, fmax(-ds0,0.0)*is0);
            mqs = fmax(mqs, fmax(-dsA,0.0)*isA);
            mqs = fmax(mqs, fmax(-dsB,0.0)*isB);
            mqz = fmax(mqz, fmax(1.0 + ds0*is0, 0.0));
            mqz = fmax(mqz, fmax(1.0 + dsA*isA, 0.0));
            mqz = fmax(mqz, fmax(1.0 + dsB*isB, 0.0));
            const double q = fmax(mqs, mqz);
            const double aaff = (q > 0.0) ? fmin(1.0, 1.0/q) : 1.0;
            const double S1t = S1v + s0*dz0 + z0*ds0 + sA*dzA + zA*dsA + sB*dzB + zB*dsB;
            const double S2t = S2v + ds0*dz0 + dsA*dzA + dsB*dzB;
            const double muaff = (SZTOT + aaff*S1t + aaff*aaff*S2t) * IMCON;
            const double sg = muaff / mu;
            smu = sg*sg*sg * mu;
            rsz0 = s0*z0 + ds0*dz0 - smu;
            rszA = sA*zA + dsA*dzA - smu;
            rszB = sB*zB + dsB*dzB - smu;
            // corrector T-scalars (overwrite)
            T0 = (z0*rp0 - rsz0) * is0;
            TA = (zA*rpA - rszA) * isA;
            TB = (zB*rpB - rszB) * isB;
        }

        // =============== Round D: corrector rhs, Woodbury sums ===============
        double rsz1[VPT], rsz2[VPT];
        {
            double d0 = 0, d1 = 0;
#pragma unroll
            for (int k = 0; k < VPT; ++k) {
                double dx = g[k];                        // affine dx
                double rp1 = s1[k] - xi[k];
                double rp2 = xi[k] + s2[k] - 1.0;
                double w1 = z1[k] * invs1[k], w2 = z2[k] * invs2[k];
                double ds1 = dx - rp1,  ds2 = -rp2 - dx;
                double dz1 = -z1[k] - w1*ds1;
                double dz2 = -z2[k] - w2*ds2;
                rsz1[k] = s1[k]*z1[k] + ds1*dz1 - smu;
                rsz2[k] = s2[k]*z2[k] + ds2*dz2 - smu;
                double rx  = EPSR*xi[k] + pi[k] + (z0 - z1[k] + z2[k] + fi[k]*(zA - zB));
                double t1 = (z1[k]*rp1 - rsz1[k]) * invs1[k];
                double t2 = (z2[k]*rp2 - rsz2[k]) * invs2[k];
                double rhs = -(rx + T0 - t1 + t2 + fi[k]*(TA - TB));
                g[k] = rhs * invD[k];
                d0 += g[k];
                d1 += fi[k] * g[k];
            }
            d0 = wsum(d0); d1 = wsum(d1);
            if (lane == 0) { wb[rb][0][wid] = d0; wb[rb][1][wid] = d1; }
        }
        __syncthreads();
        {
            const double u1 = b8sum(wb[rb][0], lane);
            const double uf = b8sum(wb[rb][1], lane);
            rb ^= 1;
            const double Y1 = (M22*u1 - M12*uf) * detinv;
            const double Y2 = (M11*uf - M12*u1) * detinv;

            // =============== Round E: corrector dir + step ====================
            double e0 = 0, e1 = 0, mqs = 0, mqz = 0;
#pragma unroll
            for (int k = 0; k < VPT; ++k) {
                double dx = g[k] - (Y1 + fi[k]*Y2) * invD[k];
                g[k] = dx;
                double rp1 = s1[k] - xi[k];
                double rp2 = xi[k] + s2[k] - 1.0;
                double ds1 = dx - rp1,  ds2 = -rp2 - dx;
                double dz1 = -(rsz1[k] + z1[k]*ds1) * invs1[k];
                double dz2 = -(rsz2[k] + z2[k]*ds2) * invs2[k];
                mqs = fmax(mqs, fmax(fmax(-ds1,0.0)*invs1[k], fmax(-ds2,0.0)*invs2[k]));
                double invz1 = 1.0 / z1[k], invz2 = 1.0 / z2[k];
                mqz = fmax(mqz, fmax(fmax(-dz1,0.0)*invz1, fmax(-dz2,0.0)*invz2));
                e0 += dx;
                e1 += fi[k] * dx;
            }
            e0 = wsum(e0); e1 = wsum(e1); mqs = wmaxr(mqs); mqz = wmaxr(mqz);
            if (lane == 0) {
                wb[rb][0][wid]=e0; wb[rb][1][wid]=e1;
                wb[rb][2][wid]=mqs; wb[rb][3][wid]=mqz;
            }
        }
        __syncthreads();
        {
            const double sdx = b8sum(wb[rb][0], lane);
            const double fdx = b8sum(wb[rb][1], lane);
            double mqs = b8max(wb[rb][2], lane);
            double mqz = b8max(wb[rb][3], lane);
            rb ^= 1;
            const double ds0 = -rp0 - sdx;
            const double dsA = -rpA - fdx;
            const double dsB = -rpB + fdx;
            const double dz0 = -(rsz0 + z0*ds0) * is0;
            const double dzA = -(rszA + zA*dsA) * isA;
            const double dzB = -(rszB + zB*dsB) * isB;
            mqs = fmax(mqs, fmax(-ds0,0.0)*is0);
            mqs = fmax(mqs, fmax(-dsA,0.0)*isA);
            mqs = fmax(mqs, fmax(-dsB,0.0)*isB);
            mqz = fmax(mqz, fmax(-dz0,0.0)*iz0);
            mqz = fmax(mqz, fmax(-dzA,0.0)*izA);
            mqz = fmax(mqz, fmax(-dzB,0.0)*izB);
            const double q  = fmax(mqs, mqz);
            const double st = (q > 0.0) ? fmin(1.0, 1.0/q) : 1.0;
            const double alpha = 0.99 * st;
            s0 += alpha*ds0;  sA += alpha*dsA;  sB += alpha*dsB;
            z0 += alpha*dz0;  zA += alpha*dzA;  zB += alpha*dzB;
            // vector update (recompute ds/dz from kept dx, rsz, invs)
#pragma unroll
            for (int k = 0; k < VPT; ++k) {
                double dx = g[k];
                double rp1 = s1[k] - xi[k];
                double rp2 = xi[k] + s2[k] - 1.0;
                double ds1 = dx - rp1,  ds2 = -rp2 - dx;
                double dz1 = -(rsz1[k] + z1[k]*ds1) * invs1[k];
                double dz2 = -(rsz2[k] + z2[k]*ds2) * invs2[k];
                xi[k] += alpha * dx;
                s1[k] += alpha * ds1;  z1[k] += alpha * dz1;
                s2[k] += alpha * ds2;  z2[k] += alpha * dz2;
            }
        }
    }

#pragma unroll
    for (int k = 0; k < VPT; ++k)
        out[i + k * T] = (float)xi[k];
}

extern "C" void kernel_launch(void* const* d_in, const int* in_sizes, int n_in,
                              void* d_out, int out_size)
{
    const float* x    = (const float*)d_in[0];
    const int*   male = (const int*)d_in[1];
    float*       out  = (float*)d_out;
    pdip_kernel<<<1, T>>>(x, male, out);
}

// round 4
// speedup vs baseline: 1.1409x; 1.1409x over previous
#include <cuda_runtime.h>
#include <cuda_bf16.h>

// ============================================================================
// CapLayerLP PDIP QP (n=1024, m=2051), diag + rank-2 KKT -> Woodbury.
// One block, 256 threads x 4 coords. fp64.
//
// Round-4: divide elimination + reduction shrinking (latency-bound kernel).
//  * per-elem divides 5->2 (paired reciprocal + fused invD, no invz at all)
//  * cross-multiplication pair-max for corrector z step (division-free reduce)
//  * analytic Sum(dx), Sum(f dx) from Woodbury sums; Sum(z ds + s dz) = -Sum(sz)
//  * scalar divides pruned and hoisted off the inter-round critical path
// ============================================================================

#define NV    1024
#define T     256
#define VPT   4
#define NW    (T/32)
#define IMCON (1.0/2051.0)
#define EPSR  1e-4
#define CCAP  10.0
#define ITERS 20

__device__ __forceinline__ double wsum(double v) {
#pragma unroll
    for (int o = 16; o > 0; o >>= 1) v += __shfl_down_sync(0xffffffffu, v, o);
    return v;
}
__device__ __forceinline__ double wmaxr(double v) {
#pragma unroll
    for (int o = 16; o > 0; o >>= 1) v = fmax(v, __shfl_down_sync(0xffffffffu, v, o));
    return v;
}
// fraction pair max: keeps (n,d) with max n/d, d>0, via cross-multiplication
__device__ __forceinline__ void wpairmax(double& n, double& d) {
#pragma unroll
    for (int o = 16; o > 0; o >>= 1) {
        double n2 = __shfl_xor_sync(0xffffffffu, n, o);
        double d2 = __shfl_xor_sync(0xffffffffu, d, o);
        if (n2 * d > n * d2) { n = n2; d = d2; }
    }
}
__device__ __forceinline__ double b8sum(const double* p, int lane) {
    double v = p[lane & 7];
#pragma unroll
    for (int o = 4; o > 0; o >>= 1) v += __shfl_xor_sync(0xffffffffu, v, o);
    return v;
}
__device__ __forceinline__ double b8max(const double* p, int lane) {
    double v = p[lane & 7];
#pragma unroll
    for (int o = 4; o > 0; o >>= 1) v = fmax(v, __shfl_xor_sync(0xffffffffu, v, o));
    return v;
}

__global__ void __launch_bounds__(T, 1)
pdip_kernel(const float* __restrict__ xin, const int* __restrict__ male,
            float* __restrict__ out)
{
    const int i    = threadIdx.x;
    const int lane = i & 31;

    __shared__ double wb[2][6][NW];

    double pi[VPT], fi[VPT];
    double xi[VPT], s1[VPT], z1[VPT], s2[VPT], z2[VPT];
#pragma unroll
    for (int k = 0; k < VPT; ++k) {
        int c = i + k * T;
        pi[k] = -(double)xin[c];
        fi[k] = (double)male[c];
        xi[k] = 0.0; s1[k] = 1.0; z1[k] = 1.0; s2[k] = 1.0; z2[k] = 1.0;
    }

    {
        double v = wsum(fi[0] + fi[1] + fi[2] + fi[3]);
        if (lane == 0) wb[0][0][i >> 5] = v;
    }
    __syncthreads();
    const double nm = b8sum(wb[0][0], lane);
    const double hA = CCAP * nm / (double)NV + 1.0;
    const double hB = -(CCAP * nm / (double)NV);

    double s0 = 1.0, sA = 1.0, sB = 1.0;
    double z0 = 1.0, zA = 1.0, zB = 1.0;
    int rb = 1;

    for (int it = 0; it < ITERS; ++it) {
        // ---- scalar reciprocals (depend only on prev state -> hoistable) ----
        const double inv_sss = 1.0 / (s0 * sA * sB);       // 1 divide -> 3 recips
        const double is0 = sA * sB * inv_sss;
        const double isA = s0 * sB * inv_sss;
        const double isB = s0 * sA * inv_sss;
        const double w0 = z0 * is0, wA = zA * isA, wB = zB * isB;
        const double M11p = s0 / z0;                        // 1/w0
        const double M22p = 1.0 / (wA + wB);

        // ============ Round A: diag + residual sums ============
        double invs1[VPT], invs2[VPT], invD[VPT];
        double a0 = 0, a1 = 0, a2 = 0, a3 = 0, a4 = 0;
#pragma unroll
        for (int k = 0; k < VPT; ++k) {
            double ss   = s1[k] * s2[k];
            double invss = 1.0 / ss;                        // divide 1
            invs1[k] = s2[k] * invss;
            invs2[k] = s1[k] * invss;
            double den = fma(EPSR, ss, fma(z1[k], s2[k], z2[k] * s1[k]));
            invD[k] = ss / den;                             // divide 2
            a0 += xi[k];
            a1 += fi[k] * xi[k];
            a2 += s1[k] * z1[k] + s2[k] * z2[k];
            a3 += invD[k];
            a4 += fi[k] * invD[k];
        }
        a0 = wsum(a0); a1 = wsum(a1); a2 = wsum(a2); a3 = wsum(a3); a4 = wsum(a4);
        if (lane == 0) {
            int w = i >> 5;
            wb[rb][0][w]=a0; wb[rb][1][w]=a1; wb[rb][2][w]=a2;
            wb[rb][3][w]=a3; wb[rb][4][w]=a4;
        }
        __syncthreads();
        const double sumx = b8sum(wb[rb][0], lane);
        const double fx   = b8sum(wb[rb][1], lane);
        const double szv  = b8sum(wb[rb][2], lane);
        const double SiD  = b8sum(wb[rb][3], lane);
        const double SfD  = b8sum(wb[rb][4], lane);
        rb ^= 1;

        const double rp0 = sumx + s0 - CCAP;
        const double rpA =  fx + sA - hA;
        const double rpB = -fx + sB - hB;
        const double SZTOT = szv + s0*z0 + sA*zA + sB*zB;
        const double mu  = SZTOT * IMCON;
        double T0 = w0*rp0 - z0;
        double TA = wA*rpA - zA;
        double TB = wB*rpB - zB;
        const double M11 = M11p + SiD;
        const double M22 = M22p + SfD;
        const double M12 = SfD;
        const double detinv = 1.0 / (M11*M22 - M12*M12);

        // ============ Round B: predictor rhs + Woodbury sums ============
        double g[VPT];
        {
            double b0 = 0, b1 = 0;
#pragma unroll
            for (int k = 0; k < VPT; ++k) {
                double w1 = z1[k] * invs1[k], w2 = z2[k] * invs2[k];
                double rp1 = s1[k] - xi[k];
                double rp2 = xi[k] + s2[k] - 1.0;
                double rx  = EPSR*xi[k] + pi[k] + (z0 - z1[k] + z2[k] + fi[k]*(zA - zB));
                double rhs = -(rx + T0 - (w1*rp1 - z1[k]) + (w2*rp2 - z2[k]) + fi[k]*(TA - TB));
                g[k] = rhs * invD[k];
                b0 += g[k];
                b1 += fi[k] * g[k];
            }
            b0 = wsum(b0); b1 = wsum(b1);
            if (lane == 0) { int w = i >> 5; wb[rb][0][w] = b0; wb[rb][1][w] = b1; }
        }
        __syncthreads();
        const double u1 = b8sum(wb[rb][0], lane);
        const double uf = b8sum(wb[rb][1], lane);
        rb ^= 1;
        const double Y1 = (M22*u1 - M12*uf) * detinv;
        const double Y2 = (M11*uf - M12*u1) * detinv;
        // analytic sums of affine dx
        const double sdx = u1 - Y1*SiD - Y2*SfD;
        const double fdx = uf - (Y1 + Y2)*SfD;
        const double ds0 = -rp0 - sdx;
        const double dsA = -rpA - fdx;
        const double dsB = -rpB + fdx;
        const double dz0 = -z0 - w0*ds0;
        const double dzA = -zA - wA*dsA;
        const double dzB = -zB - wB*dsB;
        // scalar affine ratio candidates (division-free via is*, identity for z)
        double sc_q = fmax(fmax(-ds0,0.0)*is0, fmax(fmax(-dsA,0.0)*isA, fmax(-dsB,0.0)*isB));
        sc_q = fmax(sc_q, fmax(1.0 + ds0*is0, 0.0));
        sc_q = fmax(sc_q, fmax(1.0 + dsA*isA, 0.0));
        sc_q = fmax(sc_q, fmax(1.0 + dsB*isB, 0.0));

        // ============ Round C: affine dir, step maxes, Sum(ds dz) ============
        double prod1[VPT], prod2[VPT];
        {
            double cS2 = 0, mq = sc_q;
#pragma unroll
            for (int k = 0; k < VPT; ++k) {
                double dx = g[k] - (Y1 + fi[k]*Y2) * invD[k];
                double rp1 = s1[k] - xi[k];
                double rp2 = xi[k] + s2[k] - 1.0;
                double w1 = z1[k] * invs1[k], w2 = z2[k] * invs2[k];
                double ds1 = dx - rp1,  ds2 = -rp2 - dx;
                double dz1 = -z1[k] - w1*ds1;
                double dz2 = -z2[k] - w2*ds2;
                double r1 = ds1 * invs1[k], r2 = ds2 * invs2[k];
                mq = fmax(mq, fmax(fmax(-r1, 0.0), fmax(-r2, 0.0)));           // s-side
                mq = fmax(mq, fmax(fmax(1.0 + r1, 0.0), fmax(1.0 + r2, 0.0))); // z-side identity
                prod1[k] = ds1 * dz1;
                prod2[k] = ds2 * dz2;
                cS2 += prod1[k] + prod2[k];
            }
            cS2 = wsum(cS2); mq = wmaxr(mq);
            if (lane == 0) { int w = i >> 5; wb[rb][0][w] = cS2; wb[rb][1][w] = mq; }
        }
        __syncthreads();
        double smu, rsz0, rszA, rszB;
        {
            const double S2v = b8sum(wb[rb][0], lane);
            const double q   = b8max(wb[rb][1], lane);
            rb ^= 1;
            const double aaff = (q > 0.0) ? fmin(1.0, 1.0 / q) : 1.0;
            const double S2t = S2v + ds0*dz0 + dsA*dzA + dsB*dzB;
            // Sum(z ds + s dz) = -SZTOT exactly for the affine step
            const double muaff = fma(aaff*aaff, S2t, SZTOT*(1.0 - aaff)) * IMCON;
            const double sg = muaff / mu;
            smu = sg*sg*sg * mu;
            rsz0 = s0*z0 + ds0*dz0 - smu;
            rszA = sA*zA + dsA*dzA - smu;
            rszB = sB*zB + dsB*dzB - smu;
            T0 = (z0*rp0 - rsz0) * is0;
            TA = (zA*rpA - rszA) * isA;
            TB = (zB*rpB - rszB) * isB;
        }

        // ============ Round D: corrector rhs + Woodbury sums ============
        double rsz1[VPT], rsz2[VPT];
        {
            double d0 = 0, d1 = 0;
#pragma unroll
            for (int k = 0; k < VPT; ++k) {
                rsz1[k] = s1[k]*z1[k] + prod1[k] - smu;
                rsz2[k] = s2[k]*z2[k] + prod2[k] - smu;
                double rp1 = s1[k] - xi[k];
                double rp2 = xi[k] + s2[k] - 1.0;
                double rx  = EPSR*xi[k] + pi[k] + (z0 - z1[k] + z2[k] + fi[k]*(zA - zB));
                double t1 = (z1[k]*rp1 - rsz1[k]) * invs1[k];
                double t2 = (z2[k]*rp2 - rsz2[k]) * invs2[k];
                double rhs = -(rx + T0 - t1 + t2 + fi[k]*(TA - TB));
                g[k] = rhs * invD[k];
                d0 += g[k];
                d1 += fi[k] * g[k];
            }
            d0 = wsum(d0); d1 = wsum(d1);
            if (lane == 0) { int w = i >> 5; wb[rb][0][w] = d0; wb[rb][1][w] = d1; }
        }
        __syncthreads();
        const double u1c = b8sum(wb[rb][0], lane);
        const double ufc = b8sum(wb[rb][1], lane);
        rb ^= 1;
        const double Y1c = (M22*u1c - M12*ufc) * detinv;
        const double Y2c = (M11*ufc - M12*u1c) * detinv;
        const double sdxc = u1c - Y1c*SiD - Y2c*SfD;
        const double fdxc = ufc - (Y1c + Y2c)*SfD;
        const double ds0c = -rp0 - sdxc;
        const double dsAc = -rpA - fdxc;
        const double dsBc = -rpB + fdxc;
        const double dz0c = -(rsz0 + z0*ds0c) * is0;
        const double dzAc = -(rszA + zA*dsAc) * isA;
        const double dzBc = -(rszB + zB*dsBc) * isB;
        // scalar corrector candidates: s-side plain, z-side as fraction pair
        double sc_qs = fmax(fmax(-ds0c,0.0)*is0,
                       fmax(fmax(-dsAc,0.0)*isA, fmax(-dsBc,0.0)*isB));
        double scn = fmax(-dz0c, 0.0), scd = z0;
        { double n2 = fmax(-dzAc,0.0), d2 = zA; if (n2*scd > scn*d2) { scn=n2; scd=d2; } }
        { double n2 = fmax(-dzBc,0.0), d2 = zB; if (n2*scd > scn*d2) { scn=n2; scd=d2; } }

        // ============ Round E: corrector dir + step ============
        {
            double mqs = sc_qs, pn = scn, pd = scd;
#pragma unroll
            for (int k = 0; k < VPT; ++k) {
                double dx = g[k] - (Y1c + fi[k]*Y2c) * invD[k];
                g[k] = dx;
                double rp1 = s1[k] - xi[k];
                double rp2 = xi[k] + s2[k] - 1.0;
                double ds1 = dx - rp1,  ds2 = -rp2 - dx;
                double dz1 = -(rsz1[k] + z1[k]*ds1) * invs1[k];
                double dz2 = -(rsz2[k] + z2[k]*ds2) * invs2[k];
                mqs = fmax(mqs, fmax(fmax(-ds1,0.0)*invs1[k], fmax(-ds2,0.0)*invs2[k]));
                // z-side: division-free fraction pair (cross-mult compare)
                double n1 = fmax(-dz1, 0.0), d1v = z1[k];
                double n2 = fmax(-dz2, 0.0), d2v = z2[k];
                if (n2*d1v > n1*d2v) { n1 = n2; d1v = d2v; }
                if (n1*pd > pn*d1v)  { pn = n1; pd = d1v; }
            }
            mqs = wmaxr(mqs);
            wpairmax(pn, pd);
            if (lane == 0) {
                int w = i >> 5;
                wb[rb][0][w] = mqs; wb[rb][1][w] = pn; wb[rb][2][w] = pd;
            }
        }
        __syncthreads();
        {
            double mqs = b8max(wb[rb][0], lane);
            double pn  = wb[rb][1][lane & 7];
            double pd  = wb[rb][2][lane & 7];
#pragma unroll
            for (int o = 4; o > 0; o >>= 1) {
                double n2 = __shfl_xor_sync(0xffffffffu, pn, o);
                double d2 = __shfl_xor_sync(0xffffffffu, pd, o);
                if (n2*pd > pn*d2) { pn = n2; pd = d2; }
            }
            rb ^= 1;
            // combine plain max (mqs) with fraction pn/pd; single divide for step
            if (mqs * pd > pn) { pn = mqs; pd = 1.0; }
            double st = (pn > 0.0) ? fmin(1.0, pd / pn) : 1.0;
            const double alpha = 0.99 * st;

            s0 += alpha*ds0c;  sA += alpha*dsAc;  sB += alpha*dsBc;
            z0 += alpha*dz0c;  zA += alpha*dzAc;  zB += alpha*dzBc;
#pragma unroll
            for (int k = 0; k < VPT; ++k) {
                double dx = g[k];
                double rp1 = s1[k] - xi[k];
                double rp2 = xi[k] + s2[k] - 1.0;
                double ds1 = dx - rp1,  ds2 = -rp2 - dx;
                double dz1 = -(rsz1[k] + z1[k]*ds1) * invs1[k];
                double dz2 = -(rsz2[k] + z2[k]*ds2) * invs2[k];
                xi[k] += alpha * dx;
                s1[k] += alpha * ds1;  z1[k] += alpha * dz1;
                s2[k] += alpha * ds2;  z2[k] += alpha * dz2;
            }
        }
    }

#pragma unroll
    for (int k = 0; k < VPT; ++k)
        out[i + k * T] = (float)xi[k];
}

extern "C" void kernel_launch(void* const* d_in, const int* in_sizes, int n_in,
                              void* d_out, int out_size)
{
    const float* x    = (const float*)d_in[0];
    const int*   male = (const int*)d_in[1];
    float*       out  = (float*)d_out;
    pdip_kernel<<<1, T>>>(x, male, out);
}

// round 5
// speedup vs baseline: 2.6332x; 2.3081x over previous
#include <cuda_runtime.h>
#include <cooperative_groups.h>

namespace cg = cooperative_groups;

// ============================================================================
// CapLayerLP PDIP QP (n=1024, m=2051): diag + rank-2 KKT -> Woodbury (2x2).
// Round-5: cluster of 8 CTAs x 128 threads on 8 SMs (was 1 CTA = 1 SM pinned
// at the fp64 ceiling). Block reductions -> DSMEM mailbox all-reduce:
//   warp-reduce -> CTA partial -> store into every CTA's mailbox slot
//   (map_shared_rank) -> cluster.sync -> all threads combine 8 partials in
//   fixed rank order (deterministic, replicated scalar algebra everywhere).
// Math identical to Round-4 (divide-light, analytic sums). fp64 throughout.
// ============================================================================

#define CL    8
#define T     128
#define NWARP 4
#define NV    1024
#define IMCON (1.0/2051.0)
#define EPSR  1e-4
#define CCAP  10.0
#define ITERS 20

__device__ __forceinline__ double wsum(double v) {
#pragma unroll
    for (int o = 16; o > 0; o >>= 1) v += __shfl_down_sync(0xffffffffu, v, o);
    return v;
}
__device__ __forceinline__ double wmaxr(double v) {
#pragma unroll
    for (int o = 16; o > 0; o >>= 1) v = fmax(v, __shfl_down_sync(0xffffffffu, v, o));
    return v;
}
// fraction pair max via cross-multiplication (all lanes end with the result)
__device__ __forceinline__ void wpairmax(double& n, double& d) {
#pragma unroll
    for (int o = 16; o > 0; o >>= 1) {
        double n2 = __shfl_xor_sync(0xffffffffu, n, o);
        double d2 = __shfl_xor_sync(0xffffffffu, d, o);
        if (n2 * d > n * d2) { n = n2; d = d2; }
    }
}

__global__ void __launch_bounds__(T, 1) __cluster_dims__(CL, 1, 1)
pdip_kernel(const float* __restrict__ xin, const int* __restrict__ male,
            float* __restrict__ out)
{
    cg::cluster_group cluster = cg::this_cluster();
    const unsigned rank = cluster.block_rank();
    const int i    = threadIdx.x;
    const int lane = i & 31;
    const int wid  = i >> 5;

    __shared__ double lpart[NWARP][5];     // local warp partials
    __shared__ double mbox[2][CL][5];      // double-buffered cluster mailboxes

    const int c = (int)rank * T + i;
    const double pi = -(double)xin[c];
    const double fi = (double)male[c];
    double xi = 0.0, s1 = 1.0, z1 = 1.0, s2 = 1.0, z2 = 1.0;

    // ---- init round: n_male all-reduce ----
    {
        double v = wsum(fi);
        if (lane == 0) lpart[wid][0] = v;
        __syncthreads();
        if (wid == 0 && lane == 0) {
            double t = lpart[0][0] + lpart[1][0] + lpart[2][0] + lpart[3][0];
#pragma unroll
            for (int r = 0; r < CL; ++r)
                *cluster.map_shared_rank(&mbox[0][rank][0], r) = t;
        }
        cluster.sync();
    }
    double nm = 0.0;
#pragma unroll
    for (int r = 0; r < CL; ++r) nm += mbox[0][r][0];
    const double hA = CCAP * nm / (double)NV + 1.0;
    const double hB = -(CCAP * nm / (double)NV);

    double s0 = 1.0, sA = 1.0, sB = 1.0;
    double z0 = 1.0, zA = 1.0, zB = 1.0;
    int pb = 1;

    for (int it = 0; it < ITERS; ++it) {
        // scalar reciprocals off the critical path (prev-state only)
        const double inv_sss = 1.0 / (s0 * sA * sB);
        const double is0 = sA * sB * inv_sss;
        const double isA = s0 * sB * inv_sss;
        const double isB = s0 * sA * inv_sss;
        const double w0 = z0 * is0, wA = zA * isA, wB = zB * isB;
        const double M11p = s0 / z0;
        const double M22p = 1.0 / (wA + wB);

        // ================= Round A: diag + residual sums =================
        const double ss    = s1 * s2;
        const double invss = 1.0 / ss;
        const double invs1 = s2 * invss;
        const double invs2 = s1 * invss;
        const double den   = fma((double)EPSR, ss, fma(z1, s2, z2 * s1));
        const double invD  = ss / den;
        {
            double v0 = wsum(xi);
            double v1 = wsum(fi * xi);
            double v2 = wsum(s1 * z1 + s2 * z2);
            double v3 = wsum(invD);
            double v4 = wsum(fi * invD);
            if (lane == 0) {
                lpart[wid][0] = v0; lpart[wid][1] = v1; lpart[wid][2] = v2;
                lpart[wid][3] = v3; lpart[wid][4] = v4;
            }
        }
        __syncthreads();
        if (wid == 0 && lane < 5) {
            double t = lpart[0][lane] + lpart[1][lane] + lpart[2][lane] + lpart[3][lane];
#pragma unroll
            for (int r = 0; r < CL; ++r)
                *cluster.map_shared_rank(&mbox[pb][rank][lane], r) = t;
        }
        cluster.sync();
        double sumx = 0, fx = 0, szv = 0, SiD = 0, SfD = 0;
#pragma unroll
        for (int r = 0; r < CL; ++r) {
            sumx += mbox[pb][r][0];
            fx   += mbox[pb][r][1];
            szv  += mbox[pb][r][2];
            SiD  += mbox[pb][r][3];
            SfD  += mbox[pb][r][4];
        }
        pb ^= 1;

        const double rp0 = sumx + s0 - CCAP;
        const double rpA =  fx + sA - hA;
        const double rpB = -fx + sB - hB;
        const double SZTOT = szv + s0*z0 + sA*zA + sB*zB;
        const double mu  = SZTOT * IMCON;
        double T0 = w0*rp0 - z0;
        double TA = wA*rpA - zA;
        double TB = wB*rpB - zB;
        const double M11 = M11p + SiD;
        const double M22 = M22p + SfD;
        const double M12 = SfD;
        const double detinv = 1.0 / (M11*M22 - M12*M12);

        // ================= Round B: predictor rhs + Woodbury sums ========
        const double rp1 = s1 - xi;
        const double rp2 = xi + s2 - 1.0;
        const double w1  = z1 * invs1;
        const double w2  = z2 * invs2;
        const double rx  = EPSR*xi + pi + (z0 - z1 + z2 + fi*(zA - zB));
        double g;
        {
            double rhs = -(rx + T0 - (w1*rp1 - z1) + (w2*rp2 - z2) + fi*(TA - TB));
            g = rhs * invD;
            double v0 = wsum(g);
            double v1 = wsum(fi * g);
            if (lane == 0) { lpart[wid][0] = v0; lpart[wid][1] = v1; }
        }
        __syncthreads();
        if (wid == 0 && lane < 2) {
            double t = lpart[0][lane] + lpart[1][lane] + lpart[2][lane] + lpart[3][lane];
#pragma unroll
            for (int r = 0; r < CL; ++r)
                *cluster.map_shared_rank(&mbox[pb][rank][lane], r) = t;
        }
        cluster.sync();
        double u1 = 0, uf = 0;
#pragma unroll
        for (int r = 0; r < CL; ++r) { u1 += mbox[pb][r][0]; uf += mbox[pb][r][1]; }
        pb ^= 1;

        const double Y1 = (M22*u1 - M12*uf) * detinv;
        const double Y2 = (M11*uf - M12*u1) * detinv;
        const double sdx = u1 - Y1*SiD - Y2*SfD;     // analytic Sum(dx)
        const double fdx = uf - (Y1 + Y2)*SfD;       // analytic Sum(f dx)
        const double ds0 = -rp0 - sdx;
        const double dsA = -rpA - fdx;
        const double dsB = -rpB + fdx;
        const double dz0 = -z0 - w0*ds0;
        const double dzA = -zA - wA*dsA;
        const double dzB = -zB - wB*dsB;
        double sc_q = fmax(fmax(-ds0,0.0)*is0, fmax(fmax(-dsA,0.0)*isA, fmax(-dsB,0.0)*isB));
        sc_q = fmax(sc_q, fmax(1.0 + ds0*is0, 0.0));
        sc_q = fmax(sc_q, fmax(1.0 + dsA*isA, 0.0));
        sc_q = fmax(sc_q, fmax(1.0 + dsB*isB, 0.0));

        // ========= Round C: affine dir, step max, Sum(ds dz) =============
        double prod1, prod2;
        {
            double dx  = g - (Y1 + fi*Y2) * invD;
            double ds1 = dx - rp1,  ds2 = -rp2 - dx;
            double dz1 = -z1 - w1*ds1;
            double dz2 = -z2 - w2*ds2;
            double r1 = ds1 * invs1, r2 = ds2 * invs2;
            double mq = fmax(sc_q, fmax(fmax(-r1, 0.0), fmax(-r2, 0.0)));
            mq = fmax(mq, fmax(fmax(1.0 + r1, 0.0), fmax(1.0 + r2, 0.0)));
            prod1 = ds1 * dz1;
            prod2 = ds2 * dz2;
            double v0 = wsum(prod1 + prod2);
            double v1 = wmaxr(mq);
            if (lane == 0) { lpart[wid][0] = v0; lpart[wid][1] = v1; }
        }
        __syncthreads();
        if (wid == 0 && lane == 0) {
            double t = lpart[0][0] + lpart[1][0] + lpart[2][0] + lpart[3][0];
#pragma unroll
            for (int r = 0; r < CL; ++r)
                *cluster.map_shared_rank(&mbox[pb][rank][0], r) = t;
        }
        if (wid == 0 && lane == 1) {
            double t = fmax(fmax(lpart[0][1], lpart[1][1]), fmax(lpart[2][1], lpart[3][1]));
#pragma unroll
            for (int r = 0; r < CL; ++r)
                *cluster.map_shared_rank(&mbox[pb][rank][1], r) = t;
        }
        cluster.sync();
        double S2v = 0, qmax = 0;
#pragma unroll
        for (int r = 0; r < CL; ++r) {
            S2v  += mbox[pb][r][0];
            qmax  = fmax(qmax, mbox[pb][r][1]);
        }
        pb ^= 1;

        const double aaff = (qmax > 0.0) ? fmin(1.0, 1.0 / qmax) : 1.0;
        const double S2t  = S2v + ds0*dz0 + dsA*dzA + dsB*dzB;
        const double muaff = fma(aaff*aaff, S2t, SZTOT*(1.0 - aaff)) * IMCON;
        const double sg  = muaff / mu;
        const double smu = sg*sg*sg * mu;
        const double rsz0 = s0*z0 + ds0*dz0 - smu;
        const double rszA = sA*zA + dsA*dzA - smu;
        const double rszB = sB*zB + dsB*dzB - smu;
        T0 = (z0*rp0 - rsz0) * is0;
        TA = (zA*rpA - rszA) * isA;
        TB = (zB*rpB - rszB) * isB;

        // ========= Round D: corrector rhs + Woodbury sums ================
        const double rsz1 = s1*z1 + prod1 - smu;
        const double rsz2 = s2*z2 + prod2 - smu;
        {
            double t1 = (z1*rp1 - rsz1) * invs1;
            double t2 = (z2*rp2 - rsz2) * invs2;
            double rhs = -(rx + T0 - t1 + t2 + fi*(TA - TB));
            g = rhs * invD;
            double v0 = wsum(g);
            double v1 = wsum(fi * g);
            if (lane == 0) { lpart[wid][0] = v0; lpart[wid][1] = v1; }
        }
        __syncthreads();
        if (wid == 0 && lane < 2) {
            double t = lpart[0][lane] + lpart[1][lane] + lpart[2][lane] + lpart[3][lane];
#pragma unroll
            for (int r = 0; r < CL; ++r)
                *cluster.map_shared_rank(&mbox[pb][rank][lane], r) = t;
        }
        cluster.sync();
        double u1c = 0, ufc = 0;
#pragma unroll
        for (int r = 0; r < CL; ++r) { u1c += mbox[pb][r][0]; ufc += mbox[pb][r][1]; }
        pb ^= 1;

        const double Y1c = (M22*u1c - M12*ufc) * detinv;
        const double Y2c = (M11*ufc - M12*u1c) * detinv;
        const double sdxc = u1c - Y1c*SiD - Y2c*SfD;
        const double fdxc = ufc - (Y1c + Y2c)*SfD;
        const double ds0c = -rp0 - sdxc;
        const double dsAc = -rpA - fdxc;
        const double dsBc = -rpB + fdxc;
        const double dz0c = -(rsz0 + z0*ds0c) * is0;
        const double dzAc = -(rszA + zA*dsAc) * isA;
        const double dzBc = -(rszB + zB*dsBc) * isB;
        double sc_qs = fmax(fmax(-ds0c,0.0)*is0,
                       fmax(fmax(-dsAc,0.0)*isA, fmax(-dsBc,0.0)*isB));
        double scn = fmax(-dz0c, 0.0), scd = z0;
        { double n2 = fmax(-dzAc,0.0), d2 = zA; if (n2*scd > scn*d2) { scn=n2; scd=d2; } }
        { double n2 = fmax(-dzBc,0.0), d2 = zB; if (n2*scd > scn*d2) { scn=n2; scd=d2; } }

        // ========= Round E: corrector dir + step + update ================
        double dxc, ds1c, ds2c, dz1c, dz2c;
        {
            dxc  = g - (Y1c + fi*Y2c) * invD;
            ds1c = dxc - rp1;
            ds2c = -rp2 - dxc;
            dz1c = -(rsz1 + z1*ds1c) * invs1;
            dz2c = -(rsz2 + z2*ds2c) * invs2;
            double mqs = fmax(sc_qs, fmax(fmax(-ds1c,0.0)*invs1, fmax(-ds2c,0.0)*invs2));
            double n1 = fmax(-dz1c, 0.0), d1v = z1;
            double n2 = fmax(-dz2c, 0.0), d2v = z2;
            if (n2*d1v > n1*d2v) { n1 = n2; d1v = d2v; }
            double pn = scn, pd = scd;
            if (n1*pd > pn*d1v)  { pn = n1; pd = d1v; }
            mqs = wmaxr(mqs);
            wpairmax(pn, pd);
            if (lane == 0) { lpart[wid][0] = mqs; lpart[wid][1] = pn; lpart[wid][2] = pd; }
        }
        __syncthreads();
        if (wid == 0 && lane == 0) {
            double t = fmax(fmax(lpart[0][0], lpart[1][0]), fmax(lpart[2][0], lpart[3][0]));
#pragma unroll
            for (int r = 0; r < CL; ++r)
                *cluster.map_shared_rank(&mbox[pb][rank][0], r) = t;
        }
        if (wid == 0 && lane == 1) {
            double pn = lpart[0][1], pd = lpart[0][2];
#pragma unroll
            for (int w = 1; w < NWARP; ++w) {
                double n2 = lpart[w][1], d2 = lpart[w][2];
                if (n2*pd > pn*d2) { pn = n2; pd = d2; }
            }
#pragma unroll
            for (int r = 0; r < CL; ++r) {
                *cluster.map_shared_rank(&mbox[pb][rank][1], r) = pn;
                *cluster.map_shared_rank(&mbox[pb][rank][2], r) = pd;
            }
        }
        cluster.sync();
        double mqs = 0, pn = mbox[pb][0][1], pd = mbox[pb][0][2];
#pragma unroll
        for (int r = 0; r < CL; ++r) mqs = fmax(mqs, mbox[pb][r][0]);
#pragma unroll
        for (int r = 1; r < CL; ++r) {
            double n2 = mbox[pb][r][1], d2 = mbox[pb][r][2];
            if (n2*pd > pn*d2) { pn = n2; pd = d2; }
        }
        pb ^= 1;

        if (mqs * pd > pn) { pn = mqs; pd = 1.0; }
        const double st = (pn > 0.0) ? fmin(1.0, pd / pn) : 1.0;
        const double alpha = 0.99 * st;

        s0 += alpha*ds0c;  sA += alpha*dsAc;  sB += alpha*dsBc;
        z0 += alpha*dz0c;  zA += alpha*dzAc;  zB += alpha*dzBc;
        xi += alpha*dxc;
        s1 += alpha*ds1c;  z1 += alpha*dz1c;
        s2 += alpha*ds2c;  z2 += alpha*dz2c;
    }

    out[c] = (float)xi;
}

extern "C" void kernel_launch(void* const* d_in, const int* in_sizes, int n_in,
                              void* d_out, int out_size)
{
    const float* x    = (const float*)d_in[0];
    const int*   male = (const int*)d_in[1];
    float*       out  = (float*)d_out;
    pdip_kernel<<<CL, T>>>(x, male, out);   // grid = one 8-CTA cluster
}